// round 13
// baseline (speedup 1.0000x reference)
#include <cuda_runtime.h>
#include <cuda_fp16.h>

// Fixed shapes for SPHERE_CUDA_77163382440039
static constexpr int HW  = 512 * 512;   // 262144 HT cells
static constexpr int NCH = 128;         // flat channels (B4 * C4)
static constexpr int S   = 32768;       // sphere bins
static constexpr int CAP = 128;         // bucket capacity per bin (Poisson(45.8))

// Scratch (static __device__ — no runtime allocation)
__device__ __align__(16) __half g_xTh[(size_t)HW * NCH];     // x transposed [hw][ch], fp16, 67 MB
__device__ __align__(16) float2 g_bucket[(size_t)S * CAP];   // (h bits, weight) per bin, 33.5 MB
__device__ __align__(16) int g_cursor[S];

// ---------------------------------------------------------------------------
__global__ void zero_cursor_kernel() {
    int i = blockIdx.x * blockDim.x + threadIdx.x;
    reinterpret_cast<int4*>(g_cursor)[i] = make_int4(0, 0, 0, 0);
}

// ---------------------------------------------------------------------------
// FUSED: transpose+convert (x [128][HW] fp32 -> g_xTh [HW][128] fp16) AND
// vote scatter. Single-use inputs read with __ldcs (evict-first) to keep
// freshly-written xT lines resident in L2 for accum_kernel.
__global__ __launch_bounds__(256) void fused_transpose_scatter_kernel(
    const float* __restrict__ in,
    const int* __restrict__ ht_idx,
    const int* __restrict__ sp_idx,
    const float* __restrict__ weight,
    int nvotes, int vpb) {
    __shared__ float4 tile4[32][32];    // 16 KB, [ch][swizzled hw4]
    const int t  = threadIdx.x;
    const int h0 = (blockIdx.x & 2047) * 128;
    const int r0 = (blockIdx.x >> 11) * 32;

    float4 v0, v1, v2, v3;
    {
        int hw4 = t & 31;
        int c0  = (t >> 5);
        v0 = __ldcs(reinterpret_cast<const float4*>(&in[(size_t)(r0 + c0 +  0) * HW + h0 + hw4 * 4]));
        v1 = __ldcs(reinterpret_cast<const float4*>(&in[(size_t)(r0 + c0 +  8) * HW + h0 + hw4 * 4]));
        v2 = __ldcs(reinterpret_cast<const float4*>(&in[(size_t)(r0 + c0 + 16) * HW + h0 + hw4 * 4]));
        v3 = __ldcs(reinterpret_cast<const float4*>(&in[(size_t)(r0 + c0 + 24) * HW + h0 + hw4 * 4]));
    }

    {
        int v = blockIdx.x * vpb + t;
        if (t < vpb && v < nvotes) {
            int s    = __ldcs(&sp_idx[v]);
            int h    = __ldcs(&ht_idx[v]);
            float wv = __ldcs(&weight[v]);
            int pos = atomicAdd(&g_cursor[s], 1);
            if (pos < CAP) {
                g_bucket[(size_t)s * CAP + pos] =
                    make_float2(__int_as_float(h), wv);
            }
        }
    }

    {
        int hw4 = t & 31;
        int c0  = (t >> 5);
        tile4[c0 +  0][hw4 ^ ((((c0 +  0) >> 3) & 3) << 1)] = v0;
        tile4[c0 +  8][hw4 ^ ((((c0 +  8) >> 3) & 3) << 1)] = v1;
        tile4[c0 + 16][hw4 ^ ((((c0 + 16) >> 3) & 3) << 1)] = v2;
        tile4[c0 + 24][hw4 ^ ((((c0 + 24) >> 3) & 3) << 1)] = v3;
    }
    __syncthreads();

    const float* tf = reinterpret_cast<const float*>(tile4);
    #pragma unroll
    for (int k = 0; k < 2; k++) {
        int chg  = t & 3;
        int hw_l = (t >> 5) * 8 + ((t & 31) >> 2) + k * 64;
        int swz  = (chg << 1);
        int col  = ((hw_l >> 2) ^ swz) * 4 + (hw_l & 3);
        float f0 = tf[(chg * 8 + 0) * 128 + col];
        float f1 = tf[(chg * 8 + 1) * 128 + col];
        float f2 = tf[(chg * 8 + 2) * 128 + col];
        float f3 = tf[(chg * 8 + 3) * 128 + col];
        float f4 = tf[(chg * 8 + 4) * 128 + col];
        float f5 = tf[(chg * 8 + 5) * 128 + col];
        float f6 = tf[(chg * 8 + 6) * 128 + col];
        float f7 = tf[(chg * 8 + 7) * 128 + col];
        __half2 h0p = __floats2half2_rn(f0, f1);
        __half2 h1p = __floats2half2_rn(f2, f3);
        __half2 h2p = __floats2half2_rn(f4, f5);
        __half2 h3p = __floats2half2_rn(f6, f7);
        uint4 pk;
        pk.x = *reinterpret_cast<const unsigned*>(&h0p);
        pk.y = *reinterpret_cast<const unsigned*>(&h1p);
        pk.z = *reinterpret_cast<const unsigned*>(&h2p);
        pk.w = *reinterpret_cast<const unsigned*>(&h3p);
        *reinterpret_cast<uint4*>(
            &g_xTh[(size_t)(h0 + hw_l) * NCH + r0 + chg * 8]) = pk;
    }
}

// ---------------------------------------------------------------------------
// One warp per sphere bin, TWO votes per warp-gather: lanes 0-15 = vote A,
// lanes 16-31 = vote B; each lane covers 8 channels via one 16B uint4 load.
// Unroll: 8 gathers = 16 votes per iteration, 128B/lane in flight.
// Epilogue: shfl_xor(16) merges the halves; smem-staged output transpose.
#define FMA8(P, W)                                                          \
    do {                                                                    \
        float2 _f;                                                          \
        _f = __half22float2(*reinterpret_cast<const __half2*>(&(P).x));     \
        a0.x += _f.x * (W); a0.y += _f.y * (W);                             \
        _f = __half22float2(*reinterpret_cast<const __half2*>(&(P).y));     \
        a0.z += _f.x * (W); a0.w += _f.y * (W);                             \
        _f = __half22float2(*reinterpret_cast<const __half2*>(&(P).z));     \
        a1.x += _f.x * (W); a1.y += _f.y * (W);                             \
        _f = __half22float2(*reinterpret_cast<const __half2*>(&(P).w));     \
        a1.z += _f.x * (W); a1.w += _f.y * (W);                             \
    } while (0)

__global__ __launch_bounds__(256) void accum_kernel(float* __restrict__ out) {
    const int warp = threadIdx.x >> 5;
    const int lane = threadIdx.x & 31;
    const int half = lane >> 4;          // 0: even-indexed vote, 1: odd
    const int lh   = lane & 15;          // channel group: ch [8*lh, 8*lh+8)
    const int s    = blockIdx.x * 8 + warp;

    int n = g_cursor[s];
    if (n > CAP) n = CAP;
    const float2* __restrict__ rec  = &g_bucket[(size_t)s * CAP];
    const float4* __restrict__ rec4 = reinterpret_cast<const float4*>(rec);
    const size_t col = (size_t)(lh * 8);

    float4 a0 = make_float4(0.f, 0.f, 0.f, 0.f);
    float4 a1 = make_float4(0.f, 0.f, 0.f, 0.f);

    int i = 0;
    for (; i + 16 <= n; i += 16) {
        float4 r0 = rec4[(i >> 1) + 0];
        float4 r1 = rec4[(i >> 1) + 1];
        float4 r2 = rec4[(i >> 1) + 2];
        float4 r3 = rec4[(i >> 1) + 3];
        float4 r4 = rec4[(i >> 1) + 4];
        float4 r5 = rec4[(i >> 1) + 5];
        float4 r6 = rec4[(i >> 1) + 6];
        float4 r7 = rec4[(i >> 1) + 7];

        int   h0 = __float_as_int(half ? r0.z : r0.x);
        int   h1 = __float_as_int(half ? r1.z : r1.x);
        int   h2 = __float_as_int(half ? r2.z : r2.x);
        int   h3 = __float_as_int(half ? r3.z : r3.x);
        int   h4 = __float_as_int(half ? r4.z : r4.x);
        int   h5 = __float_as_int(half ? r5.z : r5.x);
        int   h6 = __float_as_int(half ? r6.z : r6.x);
        int   h7 = __float_as_int(half ? r7.z : r7.x);
        float w0 = half ? r0.w : r0.y;
        float w1 = half ? r1.w : r1.y;
        float w2 = half ? r2.w : r2.y;
        float w3 = half ? r3.w : r3.y;
        float w4 = half ? r4.w : r4.y;
        float w5 = half ? r5.w : r5.y;
        float w6 = half ? r6.w : r6.y;
        float w7 = half ? r7.w : r7.y;

        const uint4 p0 = *reinterpret_cast<const uint4*>(&g_xTh[(size_t)h0 * NCH + col]);
        const uint4 p1 = *reinterpret_cast<const uint4*>(&g_xTh[(size_t)h1 * NCH + col]);
        const uint4 p2 = *reinterpret_cast<const uint4*>(&g_xTh[(size_t)h2 * NCH + col]);
        const uint4 p3 = *reinterpret_cast<const uint4*>(&g_xTh[(size_t)h3 * NCH + col]);
        const uint4 p4 = *reinterpret_cast<const uint4*>(&g_xTh[(size_t)h4 * NCH + col]);
        const uint4 p5 = *reinterpret_cast<const uint4*>(&g_xTh[(size_t)h5 * NCH + col]);
        const uint4 p6 = *reinterpret_cast<const uint4*>(&g_xTh[(size_t)h6 * NCH + col]);
        const uint4 p7 = *reinterpret_cast<const uint4*>(&g_xTh[(size_t)h7 * NCH + col]);

        FMA8(p0, w0); FMA8(p1, w1); FMA8(p2, w2); FMA8(p3, w3);
        FMA8(p4, w4); FMA8(p5, w5); FMA8(p6, w6); FMA8(p7, w7);
    }

    // Pairwise tail (up to 7 iterations of 2 votes).
    for (; i + 2 <= n; i += 2) {
        float4 r = rec4[i >> 1];
        int   h  = __float_as_int(half ? r.z : r.x);
        float wt = half ? r.w : r.y;
        const uint4 p = *reinterpret_cast<const uint4*>(&g_xTh[(size_t)h * NCH + col]);
        FMA8(p, wt);
    }
    // Single leftover vote (n odd): A-half carries it, B-half weight = 0.
    if (i < n) {
        float2 r = rec[i];
        int   h  = __float_as_int(r.x);
        float wt = half ? 0.f : r.y;
        const uint4 p = *reinterpret_cast<const uint4*>(&g_xTh[(size_t)h * NCH + col]);
        FMA8(p, wt);
    }

    // Merge A/B halves: after this, every lane holds the bin total for its
    // 8 channels.
    a0.x += __shfl_xor_sync(0xffffffffu, a0.x, 16);
    a0.y += __shfl_xor_sync(0xffffffffu, a0.y, 16);
    a0.z += __shfl_xor_sync(0xffffffffu, a0.z, 16);
    a0.w += __shfl_xor_sync(0xffffffffu, a0.w, 16);
    a1.x += __shfl_xor_sync(0xffffffffu, a1.x, 16);
    a1.y += __shfl_xor_sync(0xffffffffu, a1.y, 16);
    a1.z += __shfl_xor_sync(0xffffffffu, a1.z, 16);
    a1.w += __shfl_xor_sync(0xffffffffu, a1.w, 16);

    // Stage [8 bins][128 ch] in smem, then write out[ch][s0..s0+7] coalesced.
    __shared__ float sm[8][128];
    if (half == 0) {
        *reinterpret_cast<float4*>(&sm[warp][lh * 8])     = a0;
        *reinterpret_cast<float4*>(&sm[warp][lh * 8 + 4]) = a1;
    }
    __syncthreads();

    if (threadIdx.x < 128) {
        const int ch = threadIdx.x;
        const int s0 = blockIdx.x * 8;
        float4 o0 = make_float4(sm[0][ch], sm[1][ch], sm[2][ch], sm[3][ch]);
        float4 o1 = make_float4(sm[4][ch], sm[5][ch], sm[6][ch], sm[7][ch]);
        float4* dst = reinterpret_cast<float4*>(&out[(size_t)ch * S + s0]);
        dst[0] = o0;
        dst[1] = o1;
    }
}

// ---------------------------------------------------------------------------
extern "C" void kernel_launch(void* const* d_in, const int* in_sizes, int n_in,
                              void* d_out, int out_size) {
    const float* x      = (const float*)d_in[0];  // [128][262144] flat
    const int*   ht     = (const int*)d_in[1];
    const int*   sp     = (const int*)d_in[2];
    const float* w      = (const float*)d_in[3];
    float*       out    = (float*)d_out;          // [128][32768] flat
    const int    nvotes = in_sizes[1];

    // 1) Zero bucket cursors.
    zero_cursor_kernel<<<32, 256>>>();

    // 2) Fused transpose+convert AND vote scatter.
    {
        const int nblocks = 8192;                          // (HW/128) * (NCH/32)
        const int vpb = (nvotes + nblocks - 1) / nblocks;  // 184 <= 256
        fused_transpose_scatter_kernel<<<nblocks, 256>>>(x, ht, sp, w, nvotes, vpb);
    }

    // 3) Per-bin accumulation: 2 votes per gather, 16B/lane loads,
    //    16 votes/iteration + fused output transpose.
    accum_kernel<<<S / 8, 256>>>(out);
}

// round 14
// speedup vs baseline: 1.1396x; 1.1396x over previous
#include <cuda_runtime.h>
#include <cuda_fp16.h>

// Fixed shapes for SPHERE_CUDA_77163382440039
static constexpr int HW  = 512 * 512;   // 262144 HT cells
static constexpr int NCH = 128;         // flat channels (B4 * C4)
static constexpr int S   = 32768;       // sphere bins
static constexpr int CAP = 128;         // bucket capacity per bin (Poisson(45.8))

// Scratch (static __device__ — no runtime allocation)
__device__ __align__(16) __half g_xTh[(size_t)HW * NCH];     // x transposed [hw][ch], fp16, 67 MB
__device__ __align__(16) float2 g_bucket[(size_t)S * CAP];   // (h bits, weight) per bin, 33.5 MB
__device__ __align__(16) int g_cursor[S];

// ---------------------------------------------------------------------------
__global__ void zero_cursor_kernel() {
    int i = blockIdx.x * blockDim.x + threadIdx.x;
    reinterpret_cast<int4*>(g_cursor)[i] = make_int4(0, 0, 0, 0);
}

// ---------------------------------------------------------------------------
// FUSED: transpose+convert (x [128][HW] fp32 -> g_xTh [HW][128] fp16) AND
// vote scatter. Single-use inputs read with __ldcs (evict-first) to keep
// freshly-written xT lines resident in L2 for accum_kernel. (R12-proven.)
__global__ __launch_bounds__(256) void fused_transpose_scatter_kernel(
    const float* __restrict__ in,
    const int* __restrict__ ht_idx,
    const int* __restrict__ sp_idx,
    const float* __restrict__ weight,
    int nvotes, int vpb) {
    __shared__ float4 tile4[32][32];    // 16 KB, [ch][swizzled hw4]
    const int t  = threadIdx.x;
    const int h0 = (blockIdx.x & 2047) * 128;
    const int r0 = (blockIdx.x >> 11) * 32;

    float4 v0, v1, v2, v3;
    {
        int hw4 = t & 31;
        int c0  = (t >> 5);
        v0 = __ldcs(reinterpret_cast<const float4*>(&in[(size_t)(r0 + c0 +  0) * HW + h0 + hw4 * 4]));
        v1 = __ldcs(reinterpret_cast<const float4*>(&in[(size_t)(r0 + c0 +  8) * HW + h0 + hw4 * 4]));
        v2 = __ldcs(reinterpret_cast<const float4*>(&in[(size_t)(r0 + c0 + 16) * HW + h0 + hw4 * 4]));
        v3 = __ldcs(reinterpret_cast<const float4*>(&in[(size_t)(r0 + c0 + 24) * HW + h0 + hw4 * 4]));
    }

    {
        int v = blockIdx.x * vpb + t;
        if (t < vpb && v < nvotes) {
            int s    = __ldcs(&sp_idx[v]);
            int h    = __ldcs(&ht_idx[v]);
            float wv = __ldcs(&weight[v]);
            int pos = atomicAdd(&g_cursor[s], 1);
            if (pos < CAP) {
                g_bucket[(size_t)s * CAP + pos] =
                    make_float2(__int_as_float(h), wv);
            }
        }
    }

    {
        int hw4 = t & 31;
        int c0  = (t >> 5);
        tile4[c0 +  0][hw4 ^ ((((c0 +  0) >> 3) & 3) << 1)] = v0;
        tile4[c0 +  8][hw4 ^ ((((c0 +  8) >> 3) & 3) << 1)] = v1;
        tile4[c0 + 16][hw4 ^ ((((c0 + 16) >> 3) & 3) << 1)] = v2;
        tile4[c0 + 24][hw4 ^ ((((c0 + 24) >> 3) & 3) << 1)] = v3;
    }
    __syncthreads();

    const float* tf = reinterpret_cast<const float*>(tile4);
    #pragma unroll
    for (int k = 0; k < 2; k++) {
        int chg  = t & 3;
        int hw_l = (t >> 5) * 8 + ((t & 31) >> 2) + k * 64;
        int swz  = (chg << 1);
        int col  = ((hw_l >> 2) ^ swz) * 4 + (hw_l & 3);
        float f0 = tf[(chg * 8 + 0) * 128 + col];
        float f1 = tf[(chg * 8 + 1) * 128 + col];
        float f2 = tf[(chg * 8 + 2) * 128 + col];
        float f3 = tf[(chg * 8 + 3) * 128 + col];
        float f4 = tf[(chg * 8 + 4) * 128 + col];
        float f5 = tf[(chg * 8 + 5) * 128 + col];
        float f6 = tf[(chg * 8 + 6) * 128 + col];
        float f7 = tf[(chg * 8 + 7) * 128 + col];
        __half2 h0p = __floats2half2_rn(f0, f1);
        __half2 h1p = __floats2half2_rn(f2, f3);
        __half2 h2p = __floats2half2_rn(f4, f5);
        __half2 h3p = __floats2half2_rn(f6, f7);
        uint4 pk;
        pk.x = *reinterpret_cast<const unsigned*>(&h0p);
        pk.y = *reinterpret_cast<const unsigned*>(&h1p);
        pk.z = *reinterpret_cast<const unsigned*>(&h2p);
        pk.w = *reinterpret_cast<const unsigned*>(&h3p);
        *reinterpret_cast<uint4*>(
            &g_xTh[(size_t)(h0 + hw_l) * NCH + r0 + chg * 8]) = pk;
    }
}

// ---------------------------------------------------------------------------
// One warp per sphere bin; lane l owns channels [4l, 4l+4) in fp32 registers.
// NEW: per-warp cp.async prefetch of the bin's records into smem, so the hot
// loop's record reads are 29-cycle LDS instead of ~250-cycle L2 loads; the
// 8-gather batch (R6/R12-proven shape) then dominates the critical path.
__global__ __launch_bounds__(256) void accum_kernel(float* __restrict__ out) {
    __shared__ __align__(16) float2 srec[8][CAP];   // 8 KB record staging
    const int warp = threadIdx.x >> 5;
    const int lane = threadIdx.x & 31;
    const int s    = blockIdx.x * 8 + warp;

    int n = g_cursor[s];
    if (n > CAP) n = CAP;
    const float2* __restrict__ grec = &g_bucket[(size_t)s * CAP];

    // Prefetch used records (16B granules = 2 records each) via cp.async.
    {
        int gcnt = (n + 1) >> 1;    // float4 granules needed (<= 64)
        unsigned sbase = (unsigned)__cvta_generic_to_shared(&srec[warp][0]);
        if (lane < gcnt) {
            asm volatile("cp.async.ca.shared.global [%0], [%1], 16;"
                         :: "r"(sbase + lane * 16),
                            "l"(reinterpret_cast<const float4*>(grec) + lane)
                         : "memory");
        }
        if (lane + 32 < gcnt) {
            asm volatile("cp.async.ca.shared.global [%0], [%1], 16;"
                         :: "r"(sbase + (lane + 32) * 16),
                            "l"(reinterpret_cast<const float4*>(grec) + lane + 32)
                         : "memory");
        }
        asm volatile("cp.async.commit_group;");
        asm volatile("cp.async.wait_group 0;" ::: "memory");
        __syncwarp();
    }

    const float2* __restrict__ rec  = &srec[warp][0];
    const float4* __restrict__ rec4 = reinterpret_cast<const float4*>(rec);
    const size_t col = (size_t)(lane * 4);

    float4 a0 = make_float4(0.f, 0.f, 0.f, 0.f);
    float4 a1 = make_float4(0.f, 0.f, 0.f, 0.f);

    int i = 0;
    for (; i + 8 <= n; i += 8) {
        float4 ra = rec4[(i >> 1) + 0];
        float4 rb = rec4[(i >> 1) + 1];
        float4 rc = rec4[(i >> 1) + 2];
        float4 rd = rec4[(i >> 1) + 3];
        const uint2 p0 = *reinterpret_cast<const uint2*>(
            &g_xTh[(size_t)__float_as_int(ra.x) * NCH + col]);
        const uint2 p1 = *reinterpret_cast<const uint2*>(
            &g_xTh[(size_t)__float_as_int(ra.z) * NCH + col]);
        const uint2 p2 = *reinterpret_cast<const uint2*>(
            &g_xTh[(size_t)__float_as_int(rb.x) * NCH + col]);
        const uint2 p3 = *reinterpret_cast<const uint2*>(
            &g_xTh[(size_t)__float_as_int(rb.z) * NCH + col]);
        const uint2 p4 = *reinterpret_cast<const uint2*>(
            &g_xTh[(size_t)__float_as_int(rc.x) * NCH + col]);
        const uint2 p5 = *reinterpret_cast<const uint2*>(
            &g_xTh[(size_t)__float_as_int(rc.z) * NCH + col]);
        const uint2 p6 = *reinterpret_cast<const uint2*>(
            &g_xTh[(size_t)__float_as_int(rd.x) * NCH + col]);
        const uint2 p7 = *reinterpret_cast<const uint2*>(
            &g_xTh[(size_t)__float_as_int(rd.z) * NCH + col]);

        float2 f;
        f = __half22float2(*reinterpret_cast<const __half2*>(&p0.x));
        a0.x += f.x * ra.y; a0.y += f.y * ra.y;
        f = __half22float2(*reinterpret_cast<const __half2*>(&p0.y));
        a0.z += f.x * ra.y; a0.w += f.y * ra.y;
        f = __half22float2(*reinterpret_cast<const __half2*>(&p1.x));
        a1.x += f.x * ra.w; a1.y += f.y * ra.w;
        f = __half22float2(*reinterpret_cast<const __half2*>(&p1.y));
        a1.z += f.x * ra.w; a1.w += f.y * ra.w;

        f = __half22float2(*reinterpret_cast<const __half2*>(&p2.x));
        a0.x += f.x * rb.y; a0.y += f.y * rb.y;
        f = __half22float2(*reinterpret_cast<const __half2*>(&p2.y));
        a0.z += f.x * rb.y; a0.w += f.y * rb.y;
        f = __half22float2(*reinterpret_cast<const __half2*>(&p3.x));
        a1.x += f.x * rb.w; a1.y += f.y * rb.w;
        f = __half22float2(*reinterpret_cast<const __half2*>(&p3.y));
        a1.z += f.x * rb.w; a1.w += f.y * rb.w;

        f = __half22float2(*reinterpret_cast<const __half2*>(&p4.x));
        a0.x += f.x * rc.y; a0.y += f.y * rc.y;
        f = __half22float2(*reinterpret_cast<const __half2*>(&p4.y));
        a0.z += f.x * rc.y; a0.w += f.y * rc.y;
        f = __half22float2(*reinterpret_cast<const __half2*>(&p5.x));
        a1.x += f.x * rc.w; a1.y += f.y * rc.w;
        f = __half22float2(*reinterpret_cast<const __half2*>(&p5.y));
        a1.z += f.x * rc.w; a1.w += f.y * rc.w;

        f = __half22float2(*reinterpret_cast<const __half2*>(&p6.x));
        a0.x += f.x * rd.y; a0.y += f.y * rd.y;
        f = __half22float2(*reinterpret_cast<const __half2*>(&p6.y));
        a0.z += f.x * rd.y; a0.w += f.y * rd.y;
        f = __half22float2(*reinterpret_cast<const __half2*>(&p7.x));
        a1.x += f.x * rd.w; a1.y += f.y * rd.w;
        f = __half22float2(*reinterpret_cast<const __half2*>(&p7.y));
        a1.z += f.x * rd.w; a1.w += f.y * rd.w;
    }
    for (; i < n; i++) {
        float2 r0 = rec[i];
        const uint2 p0 = *reinterpret_cast<const uint2*>(
            &g_xTh[(size_t)__float_as_int(r0.x) * NCH + col]);
        float2 f;
        f = __half22float2(*reinterpret_cast<const __half2*>(&p0.x));
        a0.x += f.x * r0.y; a0.y += f.y * r0.y;
        f = __half22float2(*reinterpret_cast<const __half2*>(&p0.y));
        a0.z += f.x * r0.y; a0.w += f.y * r0.y;
    }
    a0.x += a1.x; a0.y += a1.y; a0.z += a1.z; a0.w += a1.w;

    // Stage [8 bins][128 ch] in smem, then write out[ch][s0..s0+7] coalesced.
    __shared__ float sm[8][128];
    *reinterpret_cast<float4*>(&sm[warp][lane * 4]) = a0;
    __syncthreads();

    if (threadIdx.x < 128) {
        const int ch = threadIdx.x;
        const int s0 = blockIdx.x * 8;
        float4 o0 = make_float4(sm[0][ch], sm[1][ch], sm[2][ch], sm[3][ch]);
        float4 o1 = make_float4(sm[4][ch], sm[5][ch], sm[6][ch], sm[7][ch]);
        float4* dst = reinterpret_cast<float4*>(&out[(size_t)ch * S + s0]);
        dst[0] = o0;
        dst[1] = o1;
    }
}

// ---------------------------------------------------------------------------
extern "C" void kernel_launch(void* const* d_in, const int* in_sizes, int n_in,
                              void* d_out, int out_size) {
    const float* x      = (const float*)d_in[0];  // [128][262144] flat
    const int*   ht     = (const int*)d_in[1];
    const int*   sp     = (const int*)d_in[2];
    const float* w      = (const float*)d_in[3];
    float*       out    = (float*)d_out;          // [128][32768] flat
    const int    nvotes = in_sizes[1];

    // 1) Zero bucket cursors.
    zero_cursor_kernel<<<32, 256>>>();

    // 2) Fused transpose+convert AND vote scatter.
    {
        const int nblocks = 8192;                          // (HW/128) * (NCH/32)
        const int vpb = (nvotes + nblocks - 1) / nblocks;  // 184 <= 256
        fused_transpose_scatter_kernel<<<nblocks, 256>>>(x, ht, sp, w, nvotes, vpb);
    }

    // 3) Per-bin register accumulation (R6/R12 loop + cp.async record
    //    prefetch into smem) + fused output transpose.
    accum_kernel<<<S / 8, 256>>>(out);
}

// round 15
// speedup vs baseline: 1.1441x; 1.0040x over previous
#include <cuda_runtime.h>
#include <cuda_fp16.h>

// Fixed shapes for SPHERE_CUDA_77163382440039
static constexpr int HW  = 512 * 512;   // 262144 HT cells
static constexpr int NCH = 128;         // flat channels (B4 * C4)
static constexpr int S   = 32768;       // sphere bins
static constexpr int CAP = 128;         // bucket capacity per bin (Poisson(45.8))

// Scratch (static __device__ — no runtime allocation)
__device__ __align__(16) __half g_xTh[(size_t)HW * NCH];     // x transposed [hw][ch], fp16, 67 MB
__device__ __align__(16) float2 g_bucket[(size_t)S * CAP];   // (h bits, weight) per bin, 33.5 MB
__device__ __align__(16) int g_cursor[S];

// ---------------------------------------------------------------------------
__global__ void zero_cursor_kernel() {
    int i = blockIdx.x * blockDim.x + threadIdx.x;
    reinterpret_cast<int4*>(g_cursor)[i] = make_int4(0, 0, 0, 0);
}

// ---------------------------------------------------------------------------
// FUSED: transpose+convert (x [128][HW] fp32 -> g_xTh [HW][128] fp16) AND
// vote scatter. Tile loads now go global->shared via cp.async.cg (16B, with
// L2 evict_first policy on the single-use x stream); the vote scatter runs
// while the copies are in flight, fully hiding its dependent-chain latency.
__global__ __launch_bounds__(256) void fused_transpose_scatter_kernel(
    const float* __restrict__ in,
    const int* __restrict__ ht_idx,
    const int* __restrict__ sp_idx,
    const float* __restrict__ weight,
    int nvotes, int vpb) {
    __shared__ float4 tile4[32][32];    // 16 KB, [ch][swizzled hw4]
    const int t  = threadIdx.x;
    const int h0 = (blockIdx.x & 2047) * 128;
    const int r0 = (blockIdx.x >> 11) * 32;

    // Phase 1a: async tile loads straight into swizzled smem slots.
    {
        unsigned sb = (unsigned)__cvta_generic_to_shared(&tile4[0][0]);
        unsigned long long pol;
        asm volatile("createpolicy.fractional.L2::evict_first.b64 %0, 1.0;"
                     : "=l"(pol));
        int hw4 = t & 31;
        int c0  = (t >> 5);
        #pragma unroll
        for (int k = 0; k < 4; k++) {
            int ch_l = c0 + k * 8;
            unsigned dst = sb + (unsigned)((ch_l * 32 +
                (hw4 ^ (((ch_l >> 3) & 3) << 1))) * 16);
            const float* src = &in[(size_t)(r0 + ch_l) * HW + h0 + hw4 * 4];
            asm volatile(
                "cp.async.cg.shared.global.L2::cache_hint [%0], [%1], 16, %2;"
                :: "r"(dst), "l"(src), "l"(pol) : "memory");
        }
        asm volatile("cp.async.commit_group;");
    }

    // Phase 1b: scatter this block's votes while the copies are in flight.
    {
        int v = blockIdx.x * vpb + t;
        if (t < vpb && v < nvotes) {
            int s    = __ldcs(&sp_idx[v]);
            int h    = __ldcs(&ht_idx[v]);
            float wv = __ldcs(&weight[v]);
            int pos = atomicAdd(&g_cursor[s], 1);
            if (pos < CAP) {
                g_bucket[(size_t)s * CAP + pos] =
                    make_float2(__int_as_float(h), wv);
            }
        }
    }

    asm volatile("cp.async.wait_group 0;" ::: "memory");
    __syncthreads();

    // Phase 2: conflict-free scalar smem reads -> pack 8 halves ->
    // 16B global stores in 64B full-sector runs.
    const float* tf = reinterpret_cast<const float*>(tile4);
    #pragma unroll
    for (int k = 0; k < 2; k++) {
        int chg  = t & 3;
        int hw_l = (t >> 5) * 8 + ((t & 31) >> 2) + k * 64;
        int swz  = (chg << 1);
        int col  = ((hw_l >> 2) ^ swz) * 4 + (hw_l & 3);
        float f0 = tf[(chg * 8 + 0) * 128 + col];
        float f1 = tf[(chg * 8 + 1) * 128 + col];
        float f2 = tf[(chg * 8 + 2) * 128 + col];
        float f3 = tf[(chg * 8 + 3) * 128 + col];
        float f4 = tf[(chg * 8 + 4) * 128 + col];
        float f5 = tf[(chg * 8 + 5) * 128 + col];
        float f6 = tf[(chg * 8 + 6) * 128 + col];
        float f7 = tf[(chg * 8 + 7) * 128 + col];
        __half2 h0p = __floats2half2_rn(f0, f1);
        __half2 h1p = __floats2half2_rn(f2, f3);
        __half2 h2p = __floats2half2_rn(f4, f5);
        __half2 h3p = __floats2half2_rn(f6, f7);
        uint4 pk;
        pk.x = *reinterpret_cast<const unsigned*>(&h0p);
        pk.y = *reinterpret_cast<const unsigned*>(&h1p);
        pk.z = *reinterpret_cast<const unsigned*>(&h2p);
        pk.w = *reinterpret_cast<const unsigned*>(&h3p);
        *reinterpret_cast<uint4*>(
            &g_xTh[(size_t)(h0 + hw_l) * NCH + r0 + chg * 8]) = pk;
    }
}

// ---------------------------------------------------------------------------
// One warp per sphere bin; lane l owns channels [4l, 4l+4) in fp32 registers.
// R14-proven: cp.async prefetch of the bin's records into smem, then the
// R6-shape unroll-8 gather loop off 29-cycle LDS record reads.
__global__ __launch_bounds__(256) void accum_kernel(float* __restrict__ out) {
    __shared__ __align__(16) float2 srec[8][CAP];   // 8 KB record staging
    const int warp = threadIdx.x >> 5;
    const int lane = threadIdx.x & 31;
    const int s    = blockIdx.x * 8 + warp;

    int n = g_cursor[s];
    if (n > CAP) n = CAP;
    const float2* __restrict__ grec = &g_bucket[(size_t)s * CAP];

    // Prefetch used records (16B granules = 2 records each) via cp.async.
    {
        int gcnt = (n + 1) >> 1;    // float4 granules needed (<= 64)
        unsigned sbase = (unsigned)__cvta_generic_to_shared(&srec[warp][0]);
        if (lane < gcnt) {
            asm volatile("cp.async.ca.shared.global [%0], [%1], 16;"
                         :: "r"(sbase + lane * 16),
                            "l"(reinterpret_cast<const float4*>(grec) + lane)
                         : "memory");
        }
        if (lane + 32 < gcnt) {
            asm volatile("cp.async.ca.shared.global [%0], [%1], 16;"
                         :: "r"(sbase + (lane + 32) * 16),
                            "l"(reinterpret_cast<const float4*>(grec) + lane + 32)
                         : "memory");
        }
        asm volatile("cp.async.commit_group;");
        asm volatile("cp.async.wait_group 0;" ::: "memory");
        __syncwarp();
    }

    const float2* __restrict__ rec  = &srec[warp][0];
    const float4* __restrict__ rec4 = reinterpret_cast<const float4*>(rec);
    const size_t col = (size_t)(lane * 4);

    float4 a0 = make_float4(0.f, 0.f, 0.f, 0.f);
    float4 a1 = make_float4(0.f, 0.f, 0.f, 0.f);

    int i = 0;
    for (; i + 8 <= n; i += 8) {
        float4 ra = rec4[(i >> 1) + 0];
        float4 rb = rec4[(i >> 1) + 1];
        float4 rc = rec4[(i >> 1) + 2];
        float4 rd = rec4[(i >> 1) + 3];
        const uint2 p0 = *reinterpret_cast<const uint2*>(
            &g_xTh[(size_t)__float_as_int(ra.x) * NCH + col]);
        const uint2 p1 = *reinterpret_cast<const uint2*>(
            &g_xTh[(size_t)__float_as_int(ra.z) * NCH + col]);
        const uint2 p2 = *reinterpret_cast<const uint2*>(
            &g_xTh[(size_t)__float_as_int(rb.x) * NCH + col]);
        const uint2 p3 = *reinterpret_cast<const uint2*>(
            &g_xTh[(size_t)__float_as_int(rb.z) * NCH + col]);
        const uint2 p4 = *reinterpret_cast<const uint2*>(
            &g_xTh[(size_t)__float_as_int(rc.x) * NCH + col]);
        const uint2 p5 = *reinterpret_cast<const uint2*>(
            &g_xTh[(size_t)__float_as_int(rc.z) * NCH + col]);
        const uint2 p6 = *reinterpret_cast<const uint2*>(
            &g_xTh[(size_t)__float_as_int(rd.x) * NCH + col]);
        const uint2 p7 = *reinterpret_cast<const uint2*>(
            &g_xTh[(size_t)__float_as_int(rd.z) * NCH + col]);

        float2 f;
        f = __half22float2(*reinterpret_cast<const __half2*>(&p0.x));
        a0.x += f.x * ra.y; a0.y += f.y * ra.y;
        f = __half22float2(*reinterpret_cast<const __half2*>(&p0.y));
        a0.z += f.x * ra.y; a0.w += f.y * ra.y;
        f = __half22float2(*reinterpret_cast<const __half2*>(&p1.x));
        a1.x += f.x * ra.w; a1.y += f.y * ra.w;
        f = __half22float2(*reinterpret_cast<const __half2*>(&p1.y));
        a1.z += f.x * ra.w; a1.w += f.y * ra.w;

        f = __half22float2(*reinterpret_cast<const __half2*>(&p2.x));
        a0.x += f.x * rb.y; a0.y += f.y * rb.y;
        f = __half22float2(*reinterpret_cast<const __half2*>(&p2.y));
        a0.z += f.x * rb.y; a0.w += f.y * rb.y;
        f = __half22float2(*reinterpret_cast<const __half2*>(&p3.x));
        a1.x += f.x * rb.w; a1.y += f.y * rb.w;
        f = __half22float2(*reinterpret_cast<const __half2*>(&p3.y));
        a1.z += f.x * rb.w; a1.w += f.y * rb.w;

        f = __half22float2(*reinterpret_cast<const __half2*>(&p4.x));
        a0.x += f.x * rc.y; a0.y += f.y * rc.y;
        f = __half22float2(*reinterpret_cast<const __half2*>(&p4.y));
        a0.z += f.x * rc.y; a0.w += f.y * rc.y;
        f = __half22float2(*reinterpret_cast<const __half2*>(&p5.x));
        a1.x += f.x * rc.w; a1.y += f.y * rc.w;
        f = __half22float2(*reinterpret_cast<const __half2*>(&p5.y));
        a1.z += f.x * rc.w; a1.w += f.y * rc.w;

        f = __half22float2(*reinterpret_cast<const __half2*>(&p6.x));
        a0.x += f.x * rd.y; a0.y += f.y * rd.y;
        f = __half22float2(*reinterpret_cast<const __half2*>(&p6.y));
        a0.z += f.x * rd.y; a0.w += f.y * rd.y;
        f = __half22float2(*reinterpret_cast<const __half2*>(&p7.x));
        a1.x += f.x * rd.w; a1.y += f.y * rd.w;
        f = __half22float2(*reinterpret_cast<const __half2*>(&p7.y));
        a1.z += f.x * rd.w; a1.w += f.y * rd.w;
    }
    for (; i < n; i++) {
        float2 r0 = rec[i];
        const uint2 p0 = *reinterpret_cast<const uint2*>(
            &g_xTh[(size_t)__float_as_int(r0.x) * NCH + col]);
        float2 f;
        f = __half22float2(*reinterpret_cast<const __half2*>(&p0.x));
        a0.x += f.x * r0.y; a0.y += f.y * r0.y;
        f = __half22float2(*reinterpret_cast<const __half2*>(&p0.y));
        a0.z += f.x * r0.y; a0.w += f.y * r0.y;
    }
    a0.x += a1.x; a0.y += a1.y; a0.z += a1.z; a0.w += a1.w;

    // Stage [8 bins][128 ch] in smem, then write out[ch][s0..s0+7] coalesced.
    __shared__ float sm[8][128];
    *reinterpret_cast<float4*>(&sm[warp][lane * 4]) = a0;
    __syncthreads();

    if (threadIdx.x < 128) {
        const int ch = threadIdx.x;
        const int s0 = blockIdx.x * 8;
        float4 o0 = make_float4(sm[0][ch], sm[1][ch], sm[2][ch], sm[3][ch]);
        float4 o1 = make_float4(sm[4][ch], sm[5][ch], sm[6][ch], sm[7][ch]);
        float4* dst = reinterpret_cast<float4*>(&out[(size_t)ch * S + s0]);
        dst[0] = o0;
        dst[1] = o1;
    }
}

// ---------------------------------------------------------------------------
extern "C" void kernel_launch(void* const* d_in, const int* in_sizes, int n_in,
                              void* d_out, int out_size) {
    const float* x      = (const float*)d_in[0];  // [128][262144] flat
    const int*   ht     = (const int*)d_in[1];
    const int*   sp     = (const int*)d_in[2];
    const float* w      = (const float*)d_in[3];
    float*       out    = (float*)d_out;          // [128][32768] flat
    const int    nvotes = in_sizes[1];

    // 1) Zero bucket cursors.
    zero_cursor_kernel<<<32, 256>>>();

    // 2) Fused transpose+convert AND vote scatter (cp.async tile loads with
    //    evict-first policy; scatter hidden under the async copies).
    {
        const int nblocks = 8192;                          // (HW/128) * (NCH/32)
        const int vpb = (nvotes + nblocks - 1) / nblocks;  // 184 <= 256
        fused_transpose_scatter_kernel<<<nblocks, 256>>>(x, ht, sp, w, nvotes, vpb);
    }

    // 3) Per-bin register accumulation (R14-proven) + fused output transpose.
    accum_kernel<<<S / 8, 256>>>(out);
}

// round 16
// speedup vs baseline: 1.1700x; 1.0226x over previous
#include <cuda_runtime.h>
#include <cuda_fp16.h>

// Fixed shapes for SPHERE_CUDA_77163382440039
static constexpr int HW  = 512 * 512;   // 262144 HT cells
static constexpr int NCH = 128;         // flat channels (B4 * C4)
static constexpr int S   = 32768;       // sphere bins
static constexpr int CAP = 128;         // bucket capacity per bin (Poisson(45.8))

// Scratch (static __device__ — no runtime allocation).
// g_cursor is zero-initialized at module load; accum_kernel's cursor READ is
// a destructive atomicExch(...,0), so every kernel_launch (first call and
// every graph replay) starts from all-zero cursors with no zero kernel.
__device__ __align__(16) __half g_xTh[(size_t)HW * NCH];     // x transposed [hw][ch], fp16, 67 MB
__device__ __align__(16) float2 g_bucket[(size_t)S * CAP];   // (h bits, weight) per bin, 33.5 MB
__device__ __align__(16) int g_cursor[S];

// ---------------------------------------------------------------------------
// FUSED: transpose+convert (x [128][HW] fp32 -> g_xTh [HW][128] fp16) AND
// vote scatter. Tile loads go global->shared via cp.async.cg (16B, with L2
// evict_first policy on the single-use x stream); the vote scatter runs
// while the copies are in flight. (R15-proven.)
__global__ __launch_bounds__(256) void fused_transpose_scatter_kernel(
    const float* __restrict__ in,
    const int* __restrict__ ht_idx,
    const int* __restrict__ sp_idx,
    const float* __restrict__ weight,
    int nvotes, int vpb) {
    __shared__ float4 tile4[32][32];    // 16 KB, [ch][swizzled hw4]
    const int t  = threadIdx.x;
    const int h0 = (blockIdx.x & 2047) * 128;
    const int r0 = (blockIdx.x >> 11) * 32;

    // Phase 1a: async tile loads straight into swizzled smem slots.
    {
        unsigned sb = (unsigned)__cvta_generic_to_shared(&tile4[0][0]);
        unsigned long long pol;
        asm volatile("createpolicy.fractional.L2::evict_first.b64 %0, 1.0;"
                     : "=l"(pol));
        int hw4 = t & 31;
        int c0  = (t >> 5);
        #pragma unroll
        for (int k = 0; k < 4; k++) {
            int ch_l = c0 + k * 8;
            unsigned dst = sb + (unsigned)((ch_l * 32 +
                (hw4 ^ (((ch_l >> 3) & 3) << 1))) * 16);
            const float* src = &in[(size_t)(r0 + ch_l) * HW + h0 + hw4 * 4];
            asm volatile(
                "cp.async.cg.shared.global.L2::cache_hint [%0], [%1], 16, %2;"
                :: "r"(dst), "l"(src), "l"(pol) : "memory");
        }
        asm volatile("cp.async.commit_group;");
    }

    // Phase 1b: scatter this block's votes while the copies are in flight.
    {
        int v = blockIdx.x * vpb + t;
        if (t < vpb && v < nvotes) {
            int s    = __ldcs(&sp_idx[v]);
            int h    = __ldcs(&ht_idx[v]);
            float wv = __ldcs(&weight[v]);
            int pos = atomicAdd(&g_cursor[s], 1);
            if (pos < CAP) {
                g_bucket[(size_t)s * CAP + pos] =
                    make_float2(__int_as_float(h), wv);
            }
        }
    }

    asm volatile("cp.async.wait_group 0;" ::: "memory");
    __syncthreads();

    // Phase 2: conflict-free scalar smem reads -> pack 8 halves ->
    // 16B global stores in 64B full-sector runs.
    const float* tf = reinterpret_cast<const float*>(tile4);
    #pragma unroll
    for (int k = 0; k < 2; k++) {
        int chg  = t & 3;
        int hw_l = (t >> 5) * 8 + ((t & 31) >> 2) + k * 64;
        int swz  = (chg << 1);
        int col  = ((hw_l >> 2) ^ swz) * 4 + (hw_l & 3);
        float f0 = tf[(chg * 8 + 0) * 128 + col];
        float f1 = tf[(chg * 8 + 1) * 128 + col];
        float f2 = tf[(chg * 8 + 2) * 128 + col];
        float f3 = tf[(chg * 8 + 3) * 128 + col];
        float f4 = tf[(chg * 8 + 4) * 128 + col];
        float f5 = tf[(chg * 8 + 5) * 128 + col];
        float f6 = tf[(chg * 8 + 6) * 128 + col];
        float f7 = tf[(chg * 8 + 7) * 128 + col];
        __half2 h0p = __floats2half2_rn(f0, f1);
        __half2 h1p = __floats2half2_rn(f2, f3);
        __half2 h2p = __floats2half2_rn(f4, f5);
        __half2 h3p = __floats2half2_rn(f6, f7);
        uint4 pk;
        pk.x = *reinterpret_cast<const unsigned*>(&h0p);
        pk.y = *reinterpret_cast<const unsigned*>(&h1p);
        pk.z = *reinterpret_cast<const unsigned*>(&h2p);
        pk.w = *reinterpret_cast<const unsigned*>(&h3p);
        *reinterpret_cast<uint4*>(
            &g_xTh[(size_t)(h0 + hw_l) * NCH + r0 + chg * 8]) = pk;
    }
}

// ---------------------------------------------------------------------------
// One warp per sphere bin; lane l owns channels [4l, 4l+4) in fp32 registers.
// R14/R15-proven: cp.async prefetch of the bin's records into smem, then the
// R6-shape unroll-8 gather loop off 29-cycle LDS record reads.
// NEW: the cursor read is a destructive atomicExch (lane 0 + broadcast),
// which doubles as the reset for the next launch/replay — no extra store,
// no zero kernel.
__global__ __launch_bounds__(256) void accum_kernel(float* __restrict__ out) {
    __shared__ __align__(16) float2 srec[8][CAP];   // 8 KB record staging
    const int warp = threadIdx.x >> 5;
    const int lane = threadIdx.x & 31;
    const int s    = blockIdx.x * 8 + warp;

    int n = 0;
    if (lane == 0) n = atomicExch(&g_cursor[s], 0);
    n = __shfl_sync(0xffffffffu, n, 0);
    if (n > CAP) n = CAP;
    const float2* __restrict__ grec = &g_bucket[(size_t)s * CAP];

    // Prefetch used records (16B granules = 2 records each) via cp.async.
    {
        int gcnt = (n + 1) >> 1;    // float4 granules needed (<= 64)
        unsigned sbase = (unsigned)__cvta_generic_to_shared(&srec[warp][0]);
        if (lane < gcnt) {
            asm volatile("cp.async.ca.shared.global [%0], [%1], 16;"
                         :: "r"(sbase + lane * 16),
                            "l"(reinterpret_cast<const float4*>(grec) + lane)
                         : "memory");
        }
        if (lane + 32 < gcnt) {
            asm volatile("cp.async.ca.shared.global [%0], [%1], 16;"
                         :: "r"(sbase + (lane + 32) * 16),
                            "l"(reinterpret_cast<const float4*>(grec) + lane + 32)
                         : "memory");
        }
        asm volatile("cp.async.commit_group;");
        asm volatile("cp.async.wait_group 0;" ::: "memory");
        __syncwarp();
    }

    const float2* __restrict__ rec  = &srec[warp][0];
    const float4* __restrict__ rec4 = reinterpret_cast<const float4*>(rec);
    const size_t col = (size_t)(lane * 4);

    float4 a0 = make_float4(0.f, 0.f, 0.f, 0.f);
    float4 a1 = make_float4(0.f, 0.f, 0.f, 0.f);

    int i = 0;
    for (; i + 8 <= n; i += 8) {
        float4 ra = rec4[(i >> 1) + 0];
        float4 rb = rec4[(i >> 1) + 1];
        float4 rc = rec4[(i >> 1) + 2];
        float4 rd = rec4[(i >> 1) + 3];
        const uint2 p0 = *reinterpret_cast<const uint2*>(
            &g_xTh[(size_t)__float_as_int(ra.x) * NCH + col]);
        const uint2 p1 = *reinterpret_cast<const uint2*>(
            &g_xTh[(size_t)__float_as_int(ra.z) * NCH + col]);
        const uint2 p2 = *reinterpret_cast<const uint2*>(
            &g_xTh[(size_t)__float_as_int(rb.x) * NCH + col]);
        const uint2 p3 = *reinterpret_cast<const uint2*>(
            &g_xTh[(size_t)__float_as_int(rb.z) * NCH + col]);
        const uint2 p4 = *reinterpret_cast<const uint2*>(
            &g_xTh[(size_t)__float_as_int(rc.x) * NCH + col]);
        const uint2 p5 = *reinterpret_cast<const uint2*>(
            &g_xTh[(size_t)__float_as_int(rc.z) * NCH + col]);
        const uint2 p6 = *reinterpret_cast<const uint2*>(
            &g_xTh[(size_t)__float_as_int(rd.x) * NCH + col]);
        const uint2 p7 = *reinterpret_cast<const uint2*>(
            &g_xTh[(size_t)__float_as_int(rd.z) * NCH + col]);

        float2 f;
        f = __half22float2(*reinterpret_cast<const __half2*>(&p0.x));
        a0.x += f.x * ra.y; a0.y += f.y * ra.y;
        f = __half22float2(*reinterpret_cast<const __half2*>(&p0.y));
        a0.z += f.x * ra.y; a0.w += f.y * ra.y;
        f = __half22float2(*reinterpret_cast<const __half2*>(&p1.x));
        a1.x += f.x * ra.w; a1.y += f.y * ra.w;
        f = __half22float2(*reinterpret_cast<const __half2*>(&p1.y));
        a1.z += f.x * ra.w; a1.w += f.y * ra.w;

        f = __half22float2(*reinterpret_cast<const __half2*>(&p2.x));
        a0.x += f.x * rb.y; a0.y += f.y * rb.y;
        f = __half22float2(*reinterpret_cast<const __half2*>(&p2.y));
        a0.z += f.x * rb.y; a0.w += f.y * rb.y;
        f = __half22float2(*reinterpret_cast<const __half2*>(&p3.x));
        a1.x += f.x * rb.w; a1.y += f.y * rb.w;
        f = __half22float2(*reinterpret_cast<const __half2*>(&p3.y));
        a1.z += f.x * rb.w; a1.w += f.y * rb.w;

        f = __half22float2(*reinterpret_cast<const __half2*>(&p4.x));
        a0.x += f.x * rc.y; a0.y += f.y * rc.y;
        f = __half22float2(*reinterpret_cast<const __half2*>(&p4.y));
        a0.z += f.x * rc.y; a0.w += f.y * rc.y;
        f = __half22float2(*reinterpret_cast<const __half2*>(&p5.x));
        a1.x += f.x * rc.w; a1.y += f.y * rc.w;
        f = __half22float2(*reinterpret_cast<const __half2*>(&p5.y));
        a1.z += f.x * rc.w; a1.w += f.y * rc.w;

        f = __half22float2(*reinterpret_cast<const __half2*>(&p6.x));
        a0.x += f.x * rd.y; a0.y += f.y * rd.y;
        f = __half22float2(*reinterpret_cast<const __half2*>(&p6.y));
        a0.z += f.x * rd.y; a0.w += f.y * rd.y;
        f = __half22float2(*reinterpret_cast<const __half2*>(&p7.x));
        a1.x += f.x * rd.w; a1.y += f.y * rd.w;
        f = __half22float2(*reinterpret_cast<const __half2*>(&p7.y));
        a1.z += f.x * rd.w; a1.w += f.y * rd.w;
    }
    for (; i < n; i++) {
        float2 r0 = rec[i];
        const uint2 p0 = *reinterpret_cast<const uint2*>(
            &g_xTh[(size_t)__float_as_int(r0.x) * NCH + col]);
        float2 f;
        f = __half22float2(*reinterpret_cast<const __half2*>(&p0.x));
        a0.x += f.x * r0.y; a0.y += f.y * r0.y;
        f = __half22float2(*reinterpret_cast<const __half2*>(&p0.y));
        a0.z += f.x * r0.y; a0.w += f.y * r0.y;
    }
    a0.x += a1.x; a0.y += a1.y; a0.z += a1.z; a0.w += a1.w;

    // Stage [8 bins][128 ch] in smem, then write out[ch][s0..s0+7] coalesced.
    __shared__ float sm[8][128];
    *reinterpret_cast<float4*>(&sm[warp][lane * 4]) = a0;
    __syncthreads();

    if (threadIdx.x < 128) {
        const int ch = threadIdx.x;
        const int s0 = blockIdx.x * 8;
        float4 o0 = make_float4(sm[0][ch], sm[1][ch], sm[2][ch], sm[3][ch]);
        float4 o1 = make_float4(sm[4][ch], sm[5][ch], sm[6][ch], sm[7][ch]);
        float4* dst = reinterpret_cast<float4*>(&out[(size_t)ch * S + s0]);
        dst[0] = o0;
        dst[1] = o1;
    }
}

// ---------------------------------------------------------------------------
extern "C" void kernel_launch(void* const* d_in, const int* in_sizes, int n_in,
                              void* d_out, int out_size) {
    const float* x      = (const float*)d_in[0];  // [128][262144] flat
    const int*   ht     = (const int*)d_in[1];
    const int*   sp     = (const int*)d_in[2];
    const float* w      = (const float*)d_in[3];
    float*       out    = (float*)d_out;          // [128][32768] flat
    const int    nvotes = in_sizes[1];

    // 1) Fused transpose+convert AND vote scatter. Cursors are guaranteed
    //    zero here: static init on first call, accum's atomicExch afterwards.
    {
        const int nblocks = 8192;                          // (HW/128) * (NCH/32)
        const int vpb = (nvotes + nblocks - 1) / nblocks;  // 184 <= 256
        fused_transpose_scatter_kernel<<<nblocks, 256>>>(x, ht, sp, w, nvotes, vpb);
    }

    // 2) Per-bin register accumulation (destructive cursor read + R14 record
    //    staging) + fused output transpose.
    accum_kernel<<<S / 8, 256>>>(out);
}